// round 3
// baseline (speedup 1.0000x reference)
#include <cuda_runtime.h>

// SpikeLayer: T=16 timesteps, per-step batch B=512, features D=8192.
// For each (b, d): V += x[t]; if |V| > 1 -> V = 0; out[t] = V.
// Chains independent across (b, d) -> one pass, float4 per thread.

#define TT 16
#define BB 512
#define DD 8192
// float4 elements per timestep slab
#define STRIDE4 ((BB * DD) / 4)   // 1,048,576

__global__ __launch_bounds__(256) void spike_kernel(
    const float4* __restrict__ in, float4* __restrict__ out)
{
    const unsigned idx = blockIdx.x * 256u + threadIdx.x;  // 0 .. STRIDE4-1

    float4 V = make_float4(0.f, 0.f, 0.f, 0.f);

    // Front-batch all 16 loads for MLP, then walk the chain.
    float4 x[TT];
#pragma unroll
    for (int t = 0; t < TT; ++t)
        x[t] = in[(unsigned)t * STRIDE4 + idx];

#pragma unroll
    for (int t = 0; t < TT; ++t) {
        V.x += x[t].x;  V.x = (fabsf(V.x) > 1.0f) ? 0.0f : V.x;
        V.y += x[t].y;  V.y = (fabsf(V.y) > 1.0f) ? 0.0f : V.y;
        V.z += x[t].z;  V.z = (fabsf(V.z) > 1.0f) ? 0.0f : V.z;
        V.w += x[t].w;  V.w = (fabsf(V.w) > 1.0f) ? 0.0f : V.w;
        out[(unsigned)t * STRIDE4 + idx] = V;
    }
}

extern "C" void kernel_launch(void* const* d_in, const int* in_sizes, int n_in,
                              void* d_out, int out_size)
{
    (void)in_sizes; (void)n_in; (void)out_size;
    const float4* in  = (const float4*)d_in[0];
    float4*       out = (float4*)d_out;

    const int threads = 256;
    const int blocks  = STRIDE4 / threads;  // 4096
    spike_kernel<<<blocks, threads>>>(in, out);
}

// round 4
// speedup vs baseline: 1.0084x; 1.0084x over previous
#include <cuda_runtime.h>

// SpikeLayer: T=16 timesteps, per-step batch B=512, features D=8192.
// For each (b, d): V += x[t]; if |V| > 1 -> V = 0; out[t] = V.
// Chains independent across (b, d) -> one pass, float4 per thread.
// R3: streaming cache hints (.cs) + half-batched loads/stores to group
// the read and write streams (DRAM turnaround) while keeping regs ~48.

#define TT 16
#define BB 512
#define DD 8192
#define STRIDE4 ((BB * DD) / 4)   // float4 per timestep slab = 1,048,576
#define HALF 8

__global__ __launch_bounds__(256) void spike_kernel(
    const float4* __restrict__ in, float4* __restrict__ out)
{
    const unsigned idx = blockIdx.x * 256u + threadIdx.x;  // 0 .. STRIDE4-1
    const float4* __restrict__ p = in  + idx;
    float4*       __restrict__ q = out + idx;

    float4 V = make_float4(0.f, 0.f, 0.f, 0.f);
    float4 x[HALF];

#pragma unroll
    for (int h = 0; h < 2; ++h) {
        // Batch 8 streaming loads (MLP=8 per thread)
#pragma unroll
        for (int t = 0; t < HALF; ++t)
            x[t] = __ldcs(p + (unsigned)(h * HALF + t) * STRIDE4);

        // Walk the dependency chain in registers, overwrite x[] with outputs
#pragma unroll
        for (int t = 0; t < HALF; ++t) {
            V.x += x[t].x;  V.x = (fabsf(V.x) > 1.0f) ? 0.0f : V.x;
            V.y += x[t].y;  V.y = (fabsf(V.y) > 1.0f) ? 0.0f : V.y;
            V.z += x[t].z;  V.z = (fabsf(V.z) > 1.0f) ? 0.0f : V.z;
            V.w += x[t].w;  V.w = (fabsf(V.w) > 1.0f) ? 0.0f : V.w;
            x[t] = V;
        }

        // Batch 8 streaming stores
#pragma unroll
        for (int t = 0; t < HALF; ++t)
            __stcs(q + (unsigned)(h * HALF + t) * STRIDE4, x[t]);
    }
}

extern "C" void kernel_launch(void* const* d_in, const int* in_sizes, int n_in,
                              void* d_out, int out_size)
{
    (void)in_sizes; (void)n_in; (void)out_size;
    const float4* in  = (const float4*)d_in[0];
    float4*       out = (float4*)d_out;

    const int threads = 256;
    const int blocks  = STRIDE4 / threads;  // 4096
    spike_kernel<<<blocks, threads>>>(in, out);
}

// round 5
// speedup vs baseline: 1.0190x; 1.0105x over previous
#include <cuda_runtime.h>

// SpikeLayer: T=16 timesteps, per-step batch B=512, features D=8192.
// For each (b, d): V += x[t]; if |V| > 1 -> V = 0; out[t] = V.
// Chains independent across (b, d) -> one pass, float4 per thread.
// R4: group-of-4 load/compute/store batching (MLP_p1=4) to cut cross-CTA
// L1tex queue contention & spread; streaming hints retained; lower regs
// restores occupancy and shrinks wave tails.

#define TT 16
#define BB 512
#define DD 8192
#define STRIDE4 ((BB * DD) / 4)   // float4 per timestep slab = 1,048,576
#define GRP 4

__global__ __launch_bounds__(256) void spike_kernel(
    const float4* __restrict__ in, float4* __restrict__ out)
{
    const unsigned idx = blockIdx.x * 256u + threadIdx.x;  // 0 .. STRIDE4-1
    const float4* __restrict__ p = in  + idx;
    float4*       __restrict__ q = out + idx;

    float4 V = make_float4(0.f, 0.f, 0.f, 0.f);
    float4 x[GRP];

#pragma unroll
    for (int g = 0; g < TT / GRP; ++g) {
        // Batch 4 streaming loads
#pragma unroll
        for (int t = 0; t < GRP; ++t)
            x[t] = __ldcs(p + (unsigned)(g * GRP + t) * STRIDE4);

        // Dependency chain in registers; overwrite x[] with outputs
#pragma unroll
        for (int t = 0; t < GRP; ++t) {
            V.x += x[t].x;  V.x = (fabsf(V.x) > 1.0f) ? 0.0f : V.x;
            V.y += x[t].y;  V.y = (fabsf(V.y) > 1.0f) ? 0.0f : V.y;
            V.z += x[t].z;  V.z = (fabsf(V.z) > 1.0f) ? 0.0f : V.z;
            V.w += x[t].w;  V.w = (fabsf(V.w) > 1.0f) ? 0.0f : V.w;
            x[t] = V;
        }

        // Batch 4 streaming stores
#pragma unroll
        for (int t = 0; t < GRP; ++t)
            __stcs(q + (unsigned)(g * GRP + t) * STRIDE4, x[t]);
    }
}

extern "C" void kernel_launch(void* const* d_in, const int* in_sizes, int n_in,
                              void* d_out, int out_size)
{
    (void)in_sizes; (void)n_in; (void)out_size;
    const float4* in  = (const float4*)d_in[0];
    float4*       out = (float4*)d_out;

    const int threads = 256;
    const int blocks  = STRIDE4 / threads;  // 4096
    spike_kernel<<<blocks, threads>>>(in, out);
}